// round 3
// baseline (speedup 1.0000x reference)
#include <cuda_runtime.h>

#define NBLK    128   // nodes per graph block
#define FEAT    32    // feature dim
#define THREADS 128
#define NBATCH  1024
#define QK      32    // k's per quarter
#define NQ      4     // quarters

__device__ int g_idx[NBATCH];

// Resolve index dtype defensively: jax often silently downcasts int64->int32.
// Read first 4KB as int32 words (safe under both layouts). If all odd words are
// zero, data is int64 (values < 1024 => high halves all zero); else it's int32.
__global__ void resolve_idx_kernel(const int* __restrict__ raw) {
    __shared__ int odd_nonzero;
    const int t = threadIdx.x;  // 1024 threads
    if (t == 0) odd_nonzero = 0;
    __syncthreads();
    int v = raw[t];
    if ((t & 1) && v != 0) odd_nonzero = 1;   // benign race, same value
    __syncthreads();
    int g = odd_nonzero ? raw[t] : raw[2 * t];
    if (g < 0) g = 0;
    if (g >= 1024) g = 1023;
    g_idx[t] = g;
}

__device__ __forceinline__ unsigned long long pack2(float a, float b) {
    unsigned long long r;
    asm("mov.b64 %0, {%1, %2};" : "=l"(r) : "f"(a), "f"(b));
    return r;
}
__device__ __forceinline__ void fma2(unsigned long long &d, unsigned long long a, unsigned long long b) {
    asm("fma.rn.f32x2 %0, %1, %2, %0;" : "+l"(d) : "l"(a), "l"(b));
}
__device__ __forceinline__ void unpack2(unsigned long long v, float &a, float &b) {
    asm("mov.b64 {%0, %1}, %2;" : "=f"(a), "=f"(b) : "l"(v));
}

// One CTA per batch block: out[128,32] = W[idx[b]] (128x128) @ x[b] (128x32), fp32.
// W streamed in four 16KB k-quarters through a 2x16KB double buffer (gmem->reg
// prefetch overlaps compute), x staged once (16KB). 48KB smem -> 4 CTAs/SM.
// Quarter swizzle: slot' = k4 ^ ((i>>3)&7); staging STS.128 hits the 4-phase
// minimum, compute LDS.128 the 2-phase minimum (256B distinct/warp).
__global__ void __launch_bounds__(THREADS, 4) bmm_kernel(
    const float* __restrict__ inp,
    const float* __restrict__ W,
    float* __restrict__ out)
{
    extern __shared__ float smem[];
    float* buf0 = smem;                    // 128 rows * 32 k = 4096 floats
    float* buf1 = smem + NBLK * QK;        // second W buffer
    float* xs   = smem + 2 * NBLK * QK;    // 128*32 floats

    const int blk = blockIdx.x;
    const int tid = threadIdx.x;

    const int g = g_idx[blk];
    const float4* Wg = (const float4*)(W + (long long)g * (NBLK * NBLK));
    const float4* xg = (const float4*)(inp + (long long)blk * NBLK * FEAT);

    // ---- Stage x: 1024 float4, coalesced ----
    #pragma unroll
    for (int it = 0; it < 8; ++it)
        ((float4*)xs)[tid + THREADS * it] = xg[tid + THREADS * it];

    // ---- Stage W quarter 0 ----
    #pragma unroll
    for (int it = 0; it < 8; ++it) {
        int qq = tid + THREADS * it;       // 0..1023
        int i  = qq >> 3;                  // row
        int s  = qq & 7;                   // 16B slot within quarter row
        float4 v = Wg[i * 32 + s];         // quarter 0 -> gmem slots [0,8)
        int ss = s ^ ((i >> 3) & 7);
        *(float4*)(buf0 + i * QK + ss * 4) = v;
    }
    __syncthreads();

    const int i0 = (tid & 15) * 8;
    const int f0 = (tid >> 4) * 4;
    const int sw = tid & 7;                // == ((i>>3)&7) for this thread's rows

    unsigned long long acc[8][2];
    #pragma unroll
    for (int j = 0; j < 8; ++j) { acc[j][0] = 0ull; acc[j][1] = 0ull; }

    float4 pre[8];

    #pragma unroll
    for (int q = 0; q < NQ; ++q) {
        const float* cur = (q & 1) ? buf1 : buf0;
        float*       nxt = (q & 1) ? buf0 : buf1;

        // Prefetch next quarter into registers (latency overlaps compute)
        if (q < NQ - 1) {
            #pragma unroll
            for (int it = 0; it < 8; ++it) {
                int qq = tid + THREADS * it;
                int i  = qq >> 3;
                int s  = qq & 7;
                pre[it] = Wg[i * 32 + (q + 1) * 8 + s];
            }
        }

        // Compute this quarter: 8 k4-groups
        #pragma unroll 2
        for (int k4 = 0; k4 < QK / 4; ++k4) {
            unsigned long long x2[4][2];
            #pragma unroll
            for (int kk = 0; kk < 4; ++kk) {
                ulonglong2 v = *(const ulonglong2*)(xs + (q * QK + k4 * 4 + kk) * FEAT + f0);
                x2[kk][0] = v.x; x2[kk][1] = v.y;
            }
            const int ss = (k4 ^ sw) * 4;           // swizzled word offset in row
            #pragma unroll
            for (int j = 0; j < 8; ++j) {
                float4 wv = *(const float4*)(cur + (i0 + j) * QK + ss);
                unsigned long long w2;
                w2 = pack2(wv.x, wv.x); fma2(acc[j][0], w2, x2[0][0]); fma2(acc[j][1], w2, x2[0][1]);
                w2 = pack2(wv.y, wv.y); fma2(acc[j][0], w2, x2[1][0]); fma2(acc[j][1], w2, x2[1][1]);
                w2 = pack2(wv.z, wv.z); fma2(acc[j][0], w2, x2[2][0]); fma2(acc[j][1], w2, x2[2][1]);
                w2 = pack2(wv.w, wv.w); fma2(acc[j][0], w2, x2[3][0]); fma2(acc[j][1], w2, x2[3][1]);
            }
        }

        // Drain prefetch into the other buffer
        if (q < NQ - 1) {
            #pragma unroll
            for (int it = 0; it < 8; ++it) {
                int qq = tid + THREADS * it;
                int i  = qq >> 3;
                int s  = qq & 7;
                int ss = s ^ ((i >> 3) & 7);
                *(float4*)(nxt + i * QK + ss * 4) = pre[it];
            }
        }
        __syncthreads();
    }

    // ---- Epilogue: STG.128 per row ----
    const long long obase = (long long)blk * NBLK * FEAT;
    #pragma unroll
    for (int j = 0; j < 8; ++j) {
        float4 o;
        unpack2(acc[j][0], o.x, o.y);
        unpack2(acc[j][1], o.z, o.w);
        *(float4*)(out + obase + (long long)(i0 + j) * FEAT + f0) = o;
    }
}

extern "C" void kernel_launch(void* const* d_in, const int* in_sizes, int n_in,
                              void* d_out, int out_size) {
    // Select pointers by element count (robust to metadata ordering):
    // input: 4194304 fp32; weights: 16777216 fp32; batch_idrange: 1024 ints.
    const float* inp = nullptr;
    const float* W   = nullptr;
    const void*  idx = nullptr;
    for (int i = 0; i < n_in; ++i) {
        if      (in_sizes[i] == 4194304)  inp = (const float*)d_in[i];
        else if (in_sizes[i] == 16777216) W   = (const float*)d_in[i];
        else if (in_sizes[i] == 1024)     idx = d_in[i];
    }

    resolve_idx_kernel<<<1, NBATCH>>>((const int*)idx);

    const size_t smem_bytes = (2 * NBLK * QK + NBLK * FEAT) * sizeof(float);  // 49152
    cudaFuncSetAttribute(bmm_kernel, cudaFuncAttributeMaxDynamicSharedMemorySize,
                         (int)smem_bytes);
    bmm_kernel<<<NBATCH, THREADS, smem_bytes>>>(inp, W, (float*)d_out);
}

// round 5
// speedup vs baseline: 1.3715x; 1.3715x over previous
#include <cuda_runtime.h>
#include <cstdint>

#define NBLK    128
#define FEAT    32
#define THREADS 128
#define NBATCH  1024

#define ASTRIDE 132   // floats per A row (128 + 4 pad): bank-bijective frag loads
#define BSTRIDE 40    // floats per B row (32 + 8 pad):  bank-bijective frag loads
#define A_FLOATS (NBLK * ASTRIDE)            // 16896
#define SMEM_FLOATS (A_FLOATS + NBLK * BSTRIDE)  // + 5120 = 22016 (88064 B)

__device__ int g_idx[NBATCH];

// Resolve index dtype defensively (jax silently downcasts int64->int32 without x64).
__global__ void resolve_idx_kernel(const int* __restrict__ raw) {
    __shared__ int odd_nonzero;
    const int t = threadIdx.x;  // 1024 threads
    if (t == 0) odd_nonzero = 0;
    __syncthreads();
    int v = raw[t];
    if ((t & 1) && v != 0) odd_nonzero = 1;   // benign race, same value
    __syncthreads();
    int g = odd_nonzero ? raw[t] : raw[2 * t];
    if (g < 0) g = 0;
    if (g >= 1024) g = 1023;
    g_idx[t] = g;
}

// m16n8k8 TF32 mma: D += A*B, fp32 accumulate. Operand low 13 bits ignored by HW.
__device__ __forceinline__ void mma_tf32(float* d, uint32_t a0, uint32_t a1,
                                         uint32_t a2, uint32_t a3,
                                         uint32_t b0, uint32_t b1) {
    asm volatile(
        "mma.sync.aligned.m16n8k8.row.col.f32.tf32.tf32.f32 "
        "{%0,%1,%2,%3}, {%4,%5,%6,%7}, {%8,%9}, {%0,%1,%2,%3};"
        : "+f"(d[0]), "+f"(d[1]), "+f"(d[2]), "+f"(d[3])
        : "r"(a0), "r"(a1), "r"(a2), "r"(a3), "r"(b0), "r"(b1));
}

__device__ __forceinline__ uint32_t f2u(float f) { return __float_as_uint(f); }

// Per CTA: out[128,32] = W[idx[b]] @ x[b] via 3xTF32-split mma.sync (HMMA pipe).
// A,B staged once in fp32; hi = truncate-to-tf32 (done by HW on raw bits),
// lo = a - (a & 0xFFFFE000) computed in regs. D = a*b + a_lo*b + a*b_lo.
__global__ void __launch_bounds__(THREADS, 2) bmm_mma_kernel(
    const float* __restrict__ inp,
    const float* __restrict__ W,
    float* __restrict__ out)
{
    extern __shared__ float smem[];
    float* As = smem;                 // [128][132]
    float* Bs = smem + A_FLOATS;      // [128][40]  (k-major rows, n columns)

    const int blk = blockIdx.x;
    const int tid = threadIdx.x;
    const int wid = tid >> 5;
    const int lid = tid & 31;
    const int gid = lid >> 2;         // groupID 0..7
    const int tig = lid & 3;          // thread-in-group 0..3

    const int g = g_idx[blk];
    const float4* Wg = (const float4*)(W + (long long)g * (NBLK * NBLK));
    const float4* xg = (const float4*)(inp + (long long)blk * NBLK * FEAT);

    // ---- Stage A (W): coalesced LDG.128 -> contiguous STS.128 (conflict-free) ----
    #pragma unroll 8
    for (int it = 0; it < 32; ++it) {
        int q = tid + THREADS * it;            // float4 index: row i = q>>5, slot s = q&31
        float4 v = Wg[q];
        int i = q >> 5;
        int s = q & 31;
        *(float4*)(As + i * ASTRIDE + s * 4) = v;
    }
    // ---- Stage B (x): [k][n] rows padded to 40 floats ----
    #pragma unroll
    for (int it = 0; it < 8; ++it) {
        int q = tid + THREADS * it;            // k = q>>3, f0 = (q&7)*4
        float4 v = xg[q];
        *(float4*)(Bs + (q >> 3) * BSTRIDE + (q & 7) * 4) = v;
    }
    __syncthreads();

    // Warp w computes rows [w*32, w*32+32) x all 32 cols: 2 m-tiles x 4 n-tiles.
    const int R = wid * 32;

    float d[2][4][4];
    #pragma unroll
    for (int mt = 0; mt < 2; ++mt)
        #pragma unroll
        for (int nt = 0; nt < 4; ++nt)
            #pragma unroll
            for (int e = 0; e < 4; ++e) d[mt][nt][e] = 0.0f;

    // Fragment base pointers (bank-conflict-free by stride choice):
    // A: addr = (R + mt*16 + gid [+8]) * 132 + ks*8 + tig [+4]
    // B: addr = (ks*8 + tig [+4]) * 40 + nt*8 + gid
    const float* a_base = As + (R + gid) * ASTRIDE + tig;
    const float* b_base = Bs + tig * BSTRIDE + gid;

    const uint32_t HMASK = 0xFFFFE000u;  // tf32-visible bits

    #pragma unroll 4
    for (int ks = 0; ks < 16; ++ks) {
        // Load A fragments (2 m-tiles x 4 regs) as raw fp32
        float a[2][4];
        #pragma unroll
        for (int mt = 0; mt < 2; ++mt) {
            const float* p = a_base + mt * (16 * ASTRIDE) + ks * 8;
            a[mt][0] = p[0];
            a[mt][1] = p[8 * ASTRIDE];
            a[mt][2] = p[4];
            a[mt][3] = p[8 * ASTRIDE + 4];
        }
        // Load B fragments (4 n-tiles x 2 regs)
        float b[4][2];
        #pragma unroll
        for (int nt = 0; nt < 4; ++nt) {
            const float* p = b_base + ks * (8 * BSTRIDE) + nt * 8;
            b[nt][0] = p[0];
            b[nt][1] = p[4 * BSTRIDE];
        }
        // Residuals: lo = v - truncate_tf32(v)   (exact in fp32)
        uint32_t al[2][4], bl[4][2];
        #pragma unroll
        for (int mt = 0; mt < 2; ++mt)
            #pragma unroll
            for (int e = 0; e < 4; ++e)
                al[mt][e] = f2u(a[mt][e] - __uint_as_float(f2u(a[mt][e]) & HMASK));
        #pragma unroll
        for (int nt = 0; nt < 4; ++nt)
            #pragma unroll
            for (int e = 0; e < 2; ++e)
                bl[nt][e] = f2u(b[nt][e] - __uint_as_float(f2u(b[nt][e]) & HMASK));

        // 3 passes fused on one fragment load:
        #pragma unroll
        for (int mt = 0; mt < 2; ++mt) {
            #pragma unroll
            for (int nt = 0; nt < 4; ++nt) {
                // hi*hi (raw regs: HW truncates low 13 bits)
                mma_tf32(d[mt][nt], f2u(a[mt][0]), f2u(a[mt][1]), f2u(a[mt][2]), f2u(a[mt][3]),
                         f2u(b[nt][0]), f2u(b[nt][1]));
                // lo_a * hi_b
                mma_tf32(d[mt][nt], al[mt][0], al[mt][1], al[mt][2], al[mt][3],
                         f2u(b[nt][0]), f2u(b[nt][1]));
                // hi_a * lo_b
                mma_tf32(d[mt][nt], f2u(a[mt][0]), f2u(a[mt][1]), f2u(a[mt][2]), f2u(a[mt][3]),
                         bl[nt][0], bl[nt][1]);
            }
        }
    }

    // ---- Epilogue: write D fragments straight to gmem (float2 per pair) ----
    float* ob = out + (long long)blk * NBLK * FEAT;
    #pragma unroll
    for (int mt = 0; mt < 2; ++mt) {
        const int r0 = R + mt * 16 + gid;
        #pragma unroll
        for (int nt = 0; nt < 4; ++nt) {
            const int c = nt * 8 + tig * 2;
            *(float2*)(ob + r0 * FEAT + c)       = make_float2(d[mt][nt][0], d[mt][nt][1]);
            *(float2*)(ob + (r0 + 8) * FEAT + c) = make_float2(d[mt][nt][2], d[mt][nt][3]);
        }
    }
}

extern "C" void kernel_launch(void* const* d_in, const int* in_sizes, int n_in,
                              void* d_out, int out_size) {
    // Select pointers by element count (robust to metadata ordering).
    const float* inp = nullptr;
    const float* W   = nullptr;
    const void*  idx = nullptr;
    for (int i = 0; i < n_in; ++i) {
        if      (in_sizes[i] == 4194304)  inp = (const float*)d_in[i];
        else if (in_sizes[i] == 16777216) W   = (const float*)d_in[i];
        else if (in_sizes[i] == 1024)     idx = d_in[i];
    }

    resolve_idx_kernel<<<1, NBATCH>>>((const int*)idx);

    const size_t smem_bytes = SMEM_FLOATS * sizeof(float);  // 88064
    cudaFuncSetAttribute(bmm_mma_kernel, cudaFuncAttributeMaxDynamicSharedMemorySize,
                         (int)smem_bytes);
    bmm_mma_kernel<<<NBATCH, THREADS, smem_bytes>>>(inp, W, (float*)d_out);
}

// round 6
// speedup vs baseline: 1.3861x; 1.0106x over previous
#include <cuda_runtime.h>
#include <cstdint>

#define NBLK    128
#define FEAT    32
#define THREADS 128
#define NBATCH  1024

#define BSTRIDE 40    // floats per B row (32 + 8 pad): bank-bijective frag loads

__device__ int g_idx[NBATCH];

// Resolve index dtype defensively (jax silently downcasts int64->int32 without x64).
__global__ void resolve_idx_kernel(const int* __restrict__ raw) {
    __shared__ int odd_nonzero;
    const int t = threadIdx.x;  // 1024 threads
    if (t == 0) odd_nonzero = 0;
    __syncthreads();
    int v = raw[t];
    if ((t & 1) && v != 0) odd_nonzero = 1;   // benign race, same value
    __syncthreads();
    int g = odd_nonzero ? raw[t] : raw[2 * t];
    if (g < 0) g = 0;
    if (g >= 1024) g = 1023;
    g_idx[t] = g;
}

// m16n8k8 TF32 mma: D += A*B, fp32 accumulate. HW ignores operand low 13 bits.
__device__ __forceinline__ void mma_tf32(float* d, uint32_t a0, uint32_t a1,
                                         uint32_t a2, uint32_t a3,
                                         uint32_t b0, uint32_t b1) {
    asm volatile(
        "mma.sync.aligned.m16n8k8.row.col.f32.tf32.tf32.f32 "
        "{%0,%1,%2,%3}, {%4,%5,%6,%7}, {%8,%9}, {%0,%1,%2,%3};"
        : "+f"(d[0]), "+f"(d[1]), "+f"(d[2]), "+f"(d[3])
        : "r"(a0), "r"(a1), "r"(a2), "r"(a3), "r"(b0), "r"(b1));
}

__device__ __forceinline__ uint32_t f2u(float f) { return __float_as_uint(f); }

// Per CTA: out[128,32] = W[idx[b]] @ x[b] via 3xTF32-split mma.sync.
// A fragments loaded DIRECTLY from gmem (W read exactly once; no smem staging,
// no pre-compute barrier for A), one k-step register prefetch. B (x) staged in
// 20KB static smem with pad-40 rows (conflict-free frag reads).
// D = a_hi*b_hi + a_lo*b_hi + a_hi*b_lo, residual ~2^-20.
__global__ void __launch_bounds__(THREADS, 4) bmm_mma_kernel(
    const float* __restrict__ inp,
    const float* __restrict__ W,
    float* __restrict__ out)
{
    __shared__ float Bs[NBLK * BSTRIDE];   // 20480 B

    const int blk = blockIdx.x;
    const int tid = threadIdx.x;
    const int wid = tid >> 5;
    const int lid = tid & 31;
    const int gid = lid >> 2;         // groupID 0..7
    const int tig = lid & 3;          // thread-in-group 0..3

    const int g = g_idx[blk];
    const float4* xg = (const float4*)(inp + (long long)blk * NBLK * FEAT);

    // ---- Stage B (x): [k][n] rows padded to 40 floats ----
    #pragma unroll
    for (int it = 0; it < 8; ++it) {
        int q = tid + THREADS * it;            // k = q>>3, f0 = (q&7)*4
        float4 v = xg[q];
        *(float4*)(Bs + (q >> 3) * BSTRIDE + (q & 7) * 4) = v;
    }

    // Warp w computes rows [w*32, w*32+32) x all 32 cols: 2 m-tiles x 4 n-tiles.
    const int R = wid * 32;

    // A fragment base in gmem: row = R + mt*16 + gid (+8), col = ks*8 + tig (+4)
    const float* ag = W + (long long)g * (NBLK * NBLK) + (R + gid) * NBLK + tig;

    float d[2][4][4];
    #pragma unroll
    for (int mt = 0; mt < 2; ++mt)
        #pragma unroll
        for (int nt = 0; nt < 4; ++nt)
            #pragma unroll
            for (int e = 0; e < 4; ++e) d[mt][nt][e] = 0.0f;

    const float* b_base = Bs + tig * BSTRIDE + gid;
    const uint32_t HMASK = 0xFFFFE000u;  // tf32-visible bits

    // Prefetch A fragments for ks = 0
    float an[2][4];
    #pragma unroll
    for (int mt = 0; mt < 2; ++mt) {
        const float* p = ag + mt * (16 * NBLK);
        an[mt][0] = p[0];
        an[mt][1] = p[8 * NBLK];
        an[mt][2] = p[4];
        an[mt][3] = p[8 * NBLK + 4];
    }

    __syncthreads();   // B visible to all warps

    #pragma unroll
    for (int ks = 0; ks < 16; ++ks) {
        float a[2][4];
        #pragma unroll
        for (int mt = 0; mt < 2; ++mt)
            #pragma unroll
            for (int e = 0; e < 4; ++e) a[mt][e] = an[mt][e];

        // Prefetch next k-step's A fragments (overlaps the 24 MMAs below)
        if (ks < 15) {
            #pragma unroll
            for (int mt = 0; mt < 2; ++mt) {
                const float* p = ag + mt * (16 * NBLK) + (ks + 1) * 8;
                an[mt][0] = p[0];
                an[mt][1] = p[8 * NBLK];
                an[mt][2] = p[4];
                an[mt][3] = p[8 * NBLK + 4];
            }
        }

        // Load B fragments (4 n-tiles x 2 regs) from smem
        float b[4][2];
        #pragma unroll
        for (int nt = 0; nt < 4; ++nt) {
            const float* p = b_base + ks * (8 * BSTRIDE) + nt * 8;
            b[nt][0] = p[0];
            b[nt][1] = p[4 * BSTRIDE];
        }

        // Residuals: lo = v - truncate_tf32(v)   (exact in fp32)
        uint32_t al[2][4], bl[4][2];
        #pragma unroll
        for (int mt = 0; mt < 2; ++mt)
            #pragma unroll
            for (int e = 0; e < 4; ++e)
                al[mt][e] = f2u(a[mt][e] - __uint_as_float(f2u(a[mt][e]) & HMASK));
        #pragma unroll
        for (int nt = 0; nt < 4; ++nt)
            #pragma unroll
            for (int e = 0; e < 2; ++e)
                bl[nt][e] = f2u(b[nt][e] - __uint_as_float(f2u(b[nt][e]) & HMASK));

        // 3 fused passes per (mt, nt) tile
        #pragma unroll
        for (int mt = 0; mt < 2; ++mt) {
            #pragma unroll
            for (int nt = 0; nt < 4; ++nt) {
                mma_tf32(d[mt][nt], f2u(a[mt][0]), f2u(a[mt][1]), f2u(a[mt][2]), f2u(a[mt][3]),
                         f2u(b[nt][0]), f2u(b[nt][1]));
                mma_tf32(d[mt][nt], al[mt][0], al[mt][1], al[mt][2], al[mt][3],
                         f2u(b[nt][0]), f2u(b[nt][1]));
                mma_tf32(d[mt][nt], f2u(a[mt][0]), f2u(a[mt][1]), f2u(a[mt][2]), f2u(a[mt][3]),
                         bl[nt][0], bl[nt][1]);
            }
        }
    }

    // ---- Epilogue: write D fragments straight to gmem (float2 per pair) ----
    float* ob = out + (long long)blk * NBLK * FEAT;
    #pragma unroll
    for (int mt = 0; mt < 2; ++mt) {
        const int r0 = R + mt * 16 + gid;
        #pragma unroll
        for (int nt = 0; nt < 4; ++nt) {
            const int c = nt * 8 + tig * 2;
            *(float2*)(ob + r0 * FEAT + c)       = make_float2(d[mt][nt][0], d[mt][nt][1]);
            *(float2*)(ob + (r0 + 8) * FEAT + c) = make_float2(d[mt][nt][2], d[mt][nt][3]);
        }
    }
}

extern "C" void kernel_launch(void* const* d_in, const int* in_sizes, int n_in,
                              void* d_out, int out_size) {
    // Select pointers by element count (robust to metadata ordering).
    const float* inp = nullptr;
    const float* W   = nullptr;
    const void*  idx = nullptr;
    for (int i = 0; i < n_in; ++i) {
        if      (in_sizes[i] == 4194304)  inp = (const float*)d_in[i];
        else if (in_sizes[i] == 16777216) W   = (const float*)d_in[i];
        else if (in_sizes[i] == 1024)     idx = d_in[i];
    }

    resolve_idx_kernel<<<1, NBATCH>>>((const int*)idx);
    bmm_mma_kernel<<<NBATCH, THREADS>>>(inp, W, (float*)d_out);
}

// round 7
// speedup vs baseline: 1.4955x; 1.0790x over previous
#include <cuda_runtime.h>
#include <cstdint>

#define NBLK    128
#define FEAT    32
#define THREADS 128
#define NBATCH  1024

#define AQSTRIDE 36           // floats per quarter row (32 + 4 pad); 36%32=4 -> bank=lid
#define AQ_FLOATS (NBLK * AQSTRIDE)   // 4608 floats = 18432 B per buffer
#define BSTRIDE  40           // floats per B row (32 + 8 pad): bank-bijective frag loads
#define B_OFF    (2 * AQ_FLOATS)      // 9216 floats
#define SMEM_FLOATS (B_OFF + NBLK * BSTRIDE)  // 14336 floats = 57344 B

__device__ int g_idx[NBATCH];

// Resolve index dtype defensively (jax silently downcasts int64->int32 without x64).
__global__ void resolve_idx_kernel(const int* __restrict__ raw) {
    __shared__ int odd_nonzero;
    const int t = threadIdx.x;  // 1024 threads
    if (t == 0) odd_nonzero = 0;
    __syncthreads();
    int v = raw[t];
    if ((t & 1) && v != 0) odd_nonzero = 1;   // benign race, same value
    __syncthreads();
    int g = odd_nonzero ? raw[t] : raw[2 * t];
    if (g < 0) g = 0;
    if (g >= 1024) g = 1023;
    g_idx[t] = g;
}

// m16n8k8 TF32 mma: D += A*B, fp32 accumulate. HW ignores operand low 13 bits.
__device__ __forceinline__ void mma_tf32(float* d, uint32_t a0, uint32_t a1,
                                         uint32_t a2, uint32_t a3,
                                         uint32_t b0, uint32_t b1) {
    asm volatile(
        "mma.sync.aligned.m16n8k8.row.col.f32.tf32.tf32.f32 "
        "{%0,%1,%2,%3}, {%4,%5,%6,%7}, {%8,%9}, {%0,%1,%2,%3};"
        : "+f"(d[0]), "+f"(d[1]), "+f"(d[2]), "+f"(d[3])
        : "r"(a0), "r"(a1), "r"(a2), "r"(a3), "r"(b0), "r"(b1));
}

__device__ __forceinline__ uint32_t f2u(float f) { return __float_as_uint(f); }
__device__ __forceinline__ uint32_t smem_u32(const void* p) {
    uint32_t a;
    asm("{ .reg .u64 t; cvta.to.shared.u64 t, %1; cvt.u32.u64 %0, t; }" : "=r"(a) : "l"(p));
    return a;
}
__device__ __forceinline__ void cp16(uint32_t dst, const void* src) {
    asm volatile("cp.async.cg.shared.global [%0], [%1], 16;" :: "r"(dst), "l"(src));
}
#define CP_COMMIT()  asm volatile("cp.async.commit_group;" ::: "memory")
#define CP_WAIT(n)   asm volatile("cp.async.wait_group %0;" :: "n"(n) : "memory")

// Per CTA: out[128,32] = W[idx[b]] @ x[b] via 3xTF32-split mma.sync.
// W streamed in four 18.4KB k-quarters via cp.async (LDGSTS: no L1 data-return
// wavefronts) through a 2-buffer pipeline; A fragments read from smem with
// conflict-free pad-36 rows. B staged once (pad-40). 57.3KB smem -> 4 CTAs/SM.
// D = a_hi*b_hi + a_lo*b_hi + a_hi*b_lo, residual ~2^-21.
__global__ void __launch_bounds__(THREADS, 4) bmm_mma_kernel(
    const float* __restrict__ inp,
    const float* __restrict__ W,
    float* __restrict__ out)
{
    extern __shared__ float smem[];
    float* Bs = smem + B_OFF;

    const int blk = blockIdx.x;
    const int tid = threadIdx.x;
    const int wid = tid >> 5;
    const int lid = tid & 31;
    const int gid = lid >> 2;         // groupID 0..7
    const int tig = lid & 3;          // thread-in-group 0..3

    const int g = g_idx[blk];
    const float* Wg = W + (long long)g * (NBLK * NBLK);
    const float4* xg = (const float4*)(inp + (long long)blk * NBLK * FEAT);

    // Per-thread cp.async assignment for one quarter: 8 chunks of 16B.
    // chunk q: row = q>>3, slot = q&7 (16B within quarter row).
    // STS side: 4 phases per warp-op (minimum). Quarter qk covers k in [qk*32, qk*32+32).
    #define ISSUE_QUARTER(qk, buf) do {                                          \
        const float* srcb = Wg + (qk) * 32;                                      \
        float* dstb = smem + (buf) * AQ_FLOATS;                                  \
        _Pragma("unroll")                                                        \
        for (int it = 0; it < 8; ++it) {                                         \
            int q = tid + THREADS * it;                                          \
            int row = q >> 3, slot = q & 7;                                      \
            cp16(smem_u32(dstb + row * AQSTRIDE + slot * 4),                     \
                 srcb + row * NBLK + slot * 4);                                  \
        }                                                                        \
        CP_COMMIT();                                                             \
    } while (0)

    ISSUE_QUARTER(0, 0);
    ISSUE_QUARTER(1, 1);

    // ---- Stage B (x): [k][n] rows padded to 40 floats ----
    #pragma unroll
    for (int it = 0; it < 8; ++it) {
        int q = tid + THREADS * it;            // k = q>>3, f0 = (q&7)*4
        float4 v = xg[q];
        *(float4*)(Bs + (q >> 3) * BSTRIDE + (q & 7) * 4) = v;
    }

    // Warp w computes rows [w*32, w*32+32) x all 32 cols: 2 m-tiles x 4 n-tiles.
    const int R = wid * 32;

    float d[2][4][4];
    #pragma unroll
    for (int mt = 0; mt < 2; ++mt)
        #pragma unroll
        for (int nt = 0; nt < 4; ++nt)
            #pragma unroll
            for (int e = 0; e < 4; ++e) d[mt][nt][e] = 0.0f;

    const float* b_base = Bs + tig * BSTRIDE + gid;
    const uint32_t HMASK = 0xFFFFE000u;  // tf32-visible bits

    #pragma unroll
    for (int qk = 0; qk < 4; ++qk) {
        if (qk < 3) { CP_WAIT(1); } else { CP_WAIT(0); }
        __syncthreads();                              // quarter qk visible to all warps

        const float* a_base = smem + (qk & 1) * AQ_FLOATS + (R + gid) * AQSTRIDE + tig;

        #pragma unroll
        for (int s = 0; s < 4; ++s) {                 // ks = qk*4 + s
            // A fragments (2 m-tiles x 4 regs), conflict-free LDS.32
            float a[2][4];
            #pragma unroll
            for (int mt = 0; mt < 2; ++mt) {
                const float* p = a_base + mt * (16 * AQSTRIDE) + s * 8;
                a[mt][0] = p[0];
                a[mt][1] = p[8 * AQSTRIDE];
                a[mt][2] = p[4];
                a[mt][3] = p[8 * AQSTRIDE + 4];
            }
            // B fragments (4 n-tiles x 2 regs)
            float b[4][2];
            #pragma unroll
            for (int nt = 0; nt < 4; ++nt) {
                const float* p = b_base + (qk * 4 + s) * (8 * BSTRIDE) + nt * 8;
                b[nt][0] = p[0];
                b[nt][1] = p[4 * BSTRIDE];
            }
            // Residuals: lo = v - truncate_tf32(v) (exact in fp32)
            uint32_t al[2][4], bl[4][2];
            #pragma unroll
            for (int mt = 0; mt < 2; ++mt)
                #pragma unroll
                for (int e = 0; e < 4; ++e)
                    al[mt][e] = f2u(a[mt][e] - __uint_as_float(f2u(a[mt][e]) & HMASK));
            #pragma unroll
            for (int nt = 0; nt < 4; ++nt)
                #pragma unroll
                for (int e = 0; e < 2; ++e)
                    bl[nt][e] = f2u(b[nt][e] - __uint_as_float(f2u(b[nt][e]) & HMASK));

            #pragma unroll
            for (int mt = 0; mt < 2; ++mt) {
                #pragma unroll
                for (int nt = 0; nt < 4; ++nt) {
                    mma_tf32(d[mt][nt], f2u(a[mt][0]), f2u(a[mt][1]), f2u(a[mt][2]), f2u(a[mt][3]),
                             f2u(b[nt][0]), f2u(b[nt][1]));
                    mma_tf32(d[mt][nt], al[mt][0], al[mt][1], al[mt][2], al[mt][3],
                             f2u(b[nt][0]), f2u(b[nt][1]));
                    mma_tf32(d[mt][nt], f2u(a[mt][0]), f2u(a[mt][1]), f2u(a[mt][2]), f2u(a[mt][3]),
                             bl[nt][0], bl[nt][1]);
                }
            }
        }

        __syncthreads();                              // all warps done with buffer qk&1
        if (qk + 2 < 4) ISSUE_QUARTER(qk + 2, qk & 1);
    }

    // ---- Epilogue: write D fragments straight to gmem (float2 per pair) ----
    float* ob = out + (long long)blk * NBLK * FEAT;
    #pragma unroll
    for (int mt = 0; mt < 2; ++mt) {
        const int r0 = R + mt * 16 + gid;
        #pragma unroll
        for (int nt = 0; nt < 4; ++nt) {
            const int c = nt * 8 + tig * 2;
            *(float2*)(ob + r0 * FEAT + c)       = make_float2(d[mt][nt][0], d[mt][nt][1]);
            *(float2*)(ob + (r0 + 8) * FEAT + c) = make_float2(d[mt][nt][2], d[mt][nt][3]);
        }
    }
}

extern "C" void kernel_launch(void* const* d_in, const int* in_sizes, int n_in,
                              void* d_out, int out_size) {
    // Select pointers by element count (robust to metadata ordering).
    const float* inp = nullptr;
    const float* W   = nullptr;
    const void*  idx = nullptr;
    for (int i = 0; i < n_in; ++i) {
        if      (in_sizes[i] == 4194304)  inp = (const float*)d_in[i];
        else if (in_sizes[i] == 16777216) W   = (const float*)d_in[i];
        else if (in_sizes[i] == 1024)     idx = d_in[i];
    }

    resolve_idx_kernel<<<1, NBATCH>>>((const int*)idx);

    const size_t smem_bytes = SMEM_FLOATS * sizeof(float);  // 57344
    cudaFuncSetAttribute(bmm_mma_kernel, cudaFuncAttributeMaxDynamicSharedMemorySize,
                         (int)smem_bytes);
    bmm_mma_kernel<<<NBATCH, THREADS, smem_bytes>>>(inp, W, (float*)d_out);
}

// round 8
// speedup vs baseline: 1.5227x; 1.0182x over previous
#include <cuda_runtime.h>
#include <cstdint>

#define NBLK    128
#define FEAT    32
#define THREADS 128
#define NBATCH  1024

#define NCHUNK   8            // k-chunks of 16
#define CHUNK_K  16
#define ASTRIDE  20           // floats per chunk row (16 + 4 pad): 20*gid+tig bijective mod 32
#define ACH_FLOATS (NBLK * ASTRIDE)      // 2560 floats = 10240 B per stage buffer
#define NSTAGE   3
#define BSTRIDE  40           // floats per B row (32 + 8 pad): 8*tig+gid bijective
#define B_OFF    (NSTAGE * ACH_FLOATS)   // 7680 floats
#define SMEM_FLOATS (B_OFF + NBLK * BSTRIDE)  // 12800 floats = 51200 B

__device__ int g_idx[NBATCH];

// Resolve index dtype defensively (jax silently downcasts int64->int32 without x64).
__global__ void resolve_idx_kernel(const int* __restrict__ raw) {
    __shared__ int odd_nonzero;
    const int t = threadIdx.x;  // 1024 threads
    if (t == 0) odd_nonzero = 0;
    __syncthreads();
    int v = raw[t];
    if ((t & 1) && v != 0) odd_nonzero = 1;   // benign race, same value
    __syncthreads();
    int g = odd_nonzero ? raw[t] : raw[2 * t];
    if (g < 0) g = 0;
    if (g >= 1024) g = 1023;
    g_idx[t] = g;
}

// m16n8k8 TF32 mma: D += A*B, fp32 accumulate. HW ignores operand low 13 bits.
__device__ __forceinline__ void mma_tf32(float* d, uint32_t a0, uint32_t a1,
                                         uint32_t a2, uint32_t a3,
                                         uint32_t b0, uint32_t b1) {
    asm volatile(
        "mma.sync.aligned.m16n8k8.row.col.f32.tf32.tf32.f32 "
        "{%0,%1,%2,%3}, {%4,%5,%6,%7}, {%8,%9}, {%0,%1,%2,%3};"
        : "+f"(d[0]), "+f"(d[1]), "+f"(d[2]), "+f"(d[3])
        : "r"(a0), "r"(a1), "r"(a2), "r"(a3), "r"(b0), "r"(b1));
}

__device__ __forceinline__ uint32_t f2u(float f) { return __float_as_uint(f); }
__device__ __forceinline__ uint32_t smem_u32(const void* p) {
    uint32_t a;
    asm("{ .reg .u64 t; cvta.to.shared.u64 t, %1; cvt.u32.u64 %0, t; }" : "=r"(a) : "l"(p));
    return a;
}
__device__ __forceinline__ void cp16(uint32_t dst, const void* src) {
    asm volatile("cp.async.cg.shared.global [%0], [%1], 16;" :: "r"(dst), "l"(src));
}
#define CP_COMMIT()  asm volatile("cp.async.commit_group;" ::: "memory")
#define CP_WAIT(n)   asm volatile("cp.async.wait_group %0;" :: "n"(n) : "memory")

// Per CTA: out[128,32] = W[idx[b]] @ x[b] via 3xTF32-split mma.sync.
// W streamed in eight k=16 chunks through a 3-stage cp.async ring:
// one __syncthreads per chunk; issue of chunk c+2 precedes compute of chunk c
// (2-chunk prefetch distance). 51.2KB smem -> 4 CTAs/SM resident.
// D = a_hi*b_hi + a_lo*b_hi + a_hi*b_lo, residual ~2^-21.
__global__ void __launch_bounds__(THREADS, 4) bmm_mma_kernel(
    const float* __restrict__ inp,
    const float* __restrict__ W,
    float* __restrict__ out)
{
    extern __shared__ float smem[];
    float* Bs = smem + B_OFF;

    const int blk = blockIdx.x;
    const int tid = threadIdx.x;
    const int wid = tid >> 5;
    const int lid = tid & 31;
    const int gid = lid >> 2;         // groupID 0..7
    const int tig = lid & 3;          // thread-in-group 0..3

    const int g = g_idx[blk];
    const float* Wg = W + (long long)g * (NBLK * NBLK);
    const float4* xg = (const float4*)(inp + (long long)blk * NBLK * FEAT);

    // One chunk = 128 rows x 16 floats = 512 x 16B; 4 cp.async per thread.
    // chunk element c = it*128 + tid: row = c>>2, slot = c&3.
    #define ISSUE_CHUNK(ck, buf) do {                                            \
        const float* srcb = Wg + (ck) * CHUNK_K;                                 \
        float* dstb = smem + (buf) * ACH_FLOATS;                                 \
        _Pragma("unroll")                                                        \
        for (int it = 0; it < 4; ++it) {                                         \
            int c = tid + THREADS * it;                                          \
            int row = c >> 2, slot = c & 3;                                      \
            cp16(smem_u32(dstb + row * ASTRIDE + slot * 4),                      \
                 srcb + row * NBLK + slot * 4);                                  \
        }                                                                        \
        CP_COMMIT();                                                             \
    } while (0)

    ISSUE_CHUNK(0, 0);
    ISSUE_CHUNK(1, 1);

    // ---- Stage B (x): [k][n] rows padded to 40 floats ----
    #pragma unroll
    for (int it = 0; it < 8; ++it) {
        int q = tid + THREADS * it;            // k = q>>3, f0 = (q&7)*4
        float4 v = xg[q];
        *(float4*)(Bs + (q >> 3) * BSTRIDE + (q & 7) * 4) = v;
    }

    // Warp w computes rows [w*32, w*32+32) x all 32 cols: 2 m-tiles x 4 n-tiles.
    const int R = wid * 32;

    float d[2][4][4];
    #pragma unroll
    for (int mt = 0; mt < 2; ++mt)
        #pragma unroll
        for (int nt = 0; nt < 4; ++nt)
            #pragma unroll
            for (int e = 0; e < 4; ++e) d[mt][nt][e] = 0.0f;

    const float* b_base = Bs + tig * BSTRIDE + gid;
    const uint32_t HMASK = 0xFFFFE000u;  // tf32-visible bits

    #pragma unroll
    for (int ck = 0; ck < NCHUNK; ++ck) {
        // Wait for chunk ck (groups complete in order). In-flight after this
        // iteration's issues: ck+1, ck+2 (when they exist).
        if (ck < NCHUNK - 2)      { CP_WAIT(1); }
        else if (ck == NCHUNK - 2){ CP_WAIT(1); }
        else                      { CP_WAIT(0); }
        __syncthreads();   // chunk ck visible; all warps done with buf (ck+2)%3's old chunk

        if (ck + 2 < NCHUNK) ISSUE_CHUNK(ck + 2, (ck + 2) % NSTAGE);

        const float* a_base = smem + (ck % NSTAGE) * ACH_FLOATS + (R + gid) * ASTRIDE + tig;

        #pragma unroll
        for (int s = 0; s < 2; ++s) {                 // ks = ck*2 + s
            float a[2][4];
            #pragma unroll
            for (int mt = 0; mt < 2; ++mt) {
                const float* p = a_base + mt * (16 * ASTRIDE) + s * 8;
                a[mt][0] = p[0];
                a[mt][1] = p[8 * ASTRIDE];
                a[mt][2] = p[4];
                a[mt][3] = p[8 * ASTRIDE + 4];
            }
            float b[4][2];
            #pragma unroll
            for (int nt = 0; nt < 4; ++nt) {
                const float* p = b_base + (ck * 2 + s) * (8 * BSTRIDE) + nt * 8;
                b[nt][0] = p[0];
                b[nt][1] = p[4 * BSTRIDE];
            }
            uint32_t al[2][4], bl[4][2];
            #pragma unroll
            for (int mt = 0; mt < 2; ++mt)
                #pragma unroll
                for (int e = 0; e < 4; ++e)
                    al[mt][e] = f2u(a[mt][e] - __uint_as_float(f2u(a[mt][e]) & HMASK));
            #pragma unroll
            for (int nt = 0; nt < 4; ++nt)
                #pragma unroll
                for (int e = 0; e < 2; ++e)
                    bl[nt][e] = f2u(b[nt][e] - __uint_as_float(f2u(b[nt][e]) & HMASK));

            #pragma unroll
            for (int mt = 0; mt < 2; ++mt) {
                #pragma unroll
                for (int nt = 0; nt < 4; ++nt) {
                    mma_tf32(d[mt][nt], f2u(a[mt][0]), f2u(a[mt][1]), f2u(a[mt][2]), f2u(a[mt][3]),
                             f2u(b[nt][0]), f2u(b[nt][1]));
                    mma_tf32(d[mt][nt], al[mt][0], al[mt][1], al[mt][2], al[mt][3],
                             f2u(b[nt][0]), f2u(b[nt][1]));
                    mma_tf32(d[mt][nt], f2u(a[mt][0]), f2u(a[mt][1]), f2u(a[mt][2]), f2u(a[mt][3]),
                             bl[nt][0], bl[nt][1]);
                }
            }
        }
    }

    // ---- Epilogue: write D fragments straight to gmem (float2 per pair) ----
    float* ob = out + (long long)blk * NBLK * FEAT;
    #pragma unroll
    for (int mt = 0; mt < 2; ++mt) {
        const int r0 = R + mt * 16 + gid;
        #pragma unroll
        for (int nt = 0; nt < 4; ++nt) {
            const int c = nt * 8 + tig * 2;
            *(float2*)(ob + r0 * FEAT + c)       = make_float2(d[mt][nt][0], d[mt][nt][1]);
            *(float2*)(ob + (r0 + 8) * FEAT + c) = make_float2(d[mt][nt][2], d[mt][nt][3]);
        }
    }
}

extern "C" void kernel_launch(void* const* d_in, const int* in_sizes, int n_in,
                              void* d_out, int out_size) {
    // Select pointers by element count (robust to metadata ordering).
    const float* inp = nullptr;
    const float* W   = nullptr;
    const void*  idx = nullptr;
    for (int i = 0; i < n_in; ++i) {
        if      (in_sizes[i] == 4194304)  inp = (const float*)d_in[i];
        else if (in_sizes[i] == 16777216) W   = (const float*)d_in[i];
        else if (in_sizes[i] == 1024)     idx = d_in[i];
    }

    resolve_idx_kernel<<<1, NBATCH>>>((const int*)idx);

    const size_t smem_bytes = SMEM_FLOATS * sizeof(float);  // 51200
    cudaFuncSetAttribute(bmm_mma_kernel, cudaFuncAttributeMaxDynamicSharedMemorySize,
                         (int)smem_bytes);
    bmm_mma_kernel<<<NBATCH, THREADS, smem_bytes>>>(inp, W, (float*)d_out);
}